// round 4
// baseline (speedup 1.0000x reference)
#include <cuda_runtime.h>
#include <float.h>

// Scratch (allocation-free: __device__ globals).
__device__ float g_ce[32768];
__device__ int   g_is64;   // 1 if target buffer is int64, 0 if int32

// ---------------------------------------------------------------------------
// Kernel 0: detect target dtype. For int64 targets in [0, C) (little-endian),
// every odd 32-bit word is zero. For int32 targets, odd words are uniform
// in [0, 1000) -> P(all 32 zero) = 1e-96. All probed indices < N, in-bounds
// for both layouts (int32 buffer has N words, int64 has 2N).
// ---------------------------------------------------------------------------
__global__ void detect_dtype_kernel(const int* __restrict__ tgt_w, int N)
{
    int probe = (N < 64) ? (N / 2) : 32;
    int all_zero = 1;
    for (int i = 0; i < probe; i++) {
        if (tgt_w[2 * i + 1] != 0) { all_zero = 0; break; }
    }
    g_is64 = all_zero;
}

// ---------------------------------------------------------------------------
// Kernel 1: per-row cross entropy. One warp per row, C<=1024 floats per row.
// Each lane holds 8 float4 in registers, computes warp max via shfl, then
// sum of exp, then lane 0 fetches x[target] and writes ce.
// ---------------------------------------------------------------------------
__global__ void __launch_bounds__(256)
ce_kernel(const float* __restrict__ x,
          const void* __restrict__ tgt,
          int N, int C)
{
    const int row  = blockIdx.x * 8 + (threadIdx.x >> 5);
    const int lane = threadIdx.x & 31;
    if (row >= N) return;

    const float4* rp = reinterpret_cast<const float4*>(x + (size_t)row * C);
    const int C4 = C >> 2;  // 250 for C=1000

    float4 v[8];
#pragma unroll
    for (int i = 0; i < 8; i++) {
        int c = lane + (i << 5);
        if (c < C4) {
            v[i] = rp[c];
        } else {
            v[i] = make_float4(-FLT_MAX, -FLT_MAX, -FLT_MAX, -FLT_MAX);
        }
    }

    // local max
    float m = -FLT_MAX;
#pragma unroll
    for (int i = 0; i < 8; i++)
        m = fmaxf(m, fmaxf(fmaxf(v[i].x, v[i].y), fmaxf(v[i].z, v[i].w)));
    // warp max
#pragma unroll
    for (int o = 16; o; o >>= 1)
        m = fmaxf(m, __shfl_xor_sync(0xFFFFFFFFu, m, o));

    // sum of exp(x - m); padding lanes contribute exp(-inf) = 0
    float s = 0.f;
#pragma unroll
    for (int i = 0; i < 8; i++) {
        s += __expf(v[i].x - m);
        s += __expf(v[i].y - m);
        s += __expf(v[i].z - m);
        s += __expf(v[i].w - m);
    }
#pragma unroll
    for (int o = 16; o; o >>= 1)
        s += __shfl_xor_sync(0xFFFFFFFFu, s, o);

    if (lane == 0) {
        long long t;
        if (g_is64) t = reinterpret_cast<const long long*>(tgt)[row];
        else        t = reinterpret_cast<const int*>(tgt)[row];
        if (t < 0) t = 0;
        if (t >= C) t = C - 1;
        float xt = x[(size_t)row * C + (int)t];
        g_ce[row] = m + __logf(s) - xt;
    }
}

// ---------------------------------------------------------------------------
// Kernel 2: single CTA, 1024 threads x 32 values in registers.
// (1) MSB-first radix select on order-preserving uint keys -> exact value at
//     descending rank k (exact tie semantics, matches sorted_desc[k]).
// (2) masked sum of values with key >= lamkey (<=> ce >= lam), / N.
// ---------------------------------------------------------------------------
__global__ void __launch_bounds__(1024)
select_mean_kernel(float* __restrict__ out, int N, int k)
{
    const int tid = threadIdx.x;
    const int T = 1024;
    const int PER = 32;  // 32768 / 1024

    float    val[PER];
    unsigned key[PER];
#pragma unroll
    for (int i = 0; i < PER; i++) {
        int idx = tid + i * T;
        float f = (idx < N) ? g_ce[idx] : -FLT_MAX;
        val[i] = (idx < N) ? f : 0.f;
        unsigned b = __float_as_uint(f);
        key[i] = (b & 0x80000000u) ? ~b : (b | 0x80000000u);
    }

    __shared__ int      s_cnt[32];
    __shared__ unsigned s_prefix;
    __shared__ float    s_sum[32];

    if (tid == 0) s_prefix = 0u;
    __syncthreads();

    unsigned prefix = 0u;
    int rank = k;  // maintained on tid 0 only

    for (int bit = 31; bit >= 0; bit--) {
        const unsigned bm = 1u << bit;
        const unsigned himask = ~((bm << 1) - 1u);  // bits strictly above 'bit'

        int c = 0;
#pragma unroll
        for (int i = 0; i < PER; i++)
            if (((key[i] & himask) == prefix) && (key[i] & bm)) c++;
#pragma unroll
        for (int o = 16; o; o >>= 1)
            c += __shfl_xor_sync(0xFFFFFFFFu, c, o);
        if ((tid & 31) == 0) s_cnt[tid >> 5] = c;
        __syncthreads();

        if (tid == 0) {
            int tot = 0;
#pragma unroll
            for (int w = 0; w < 32; w++) tot += s_cnt[w];
            if (rank < tot) s_prefix |= bm;  // k-th largest in the '1' group
            else            rank -= tot;     // skip the '1' group (tid0-local)
        }
        __syncthreads();
        prefix = s_prefix;
        __syncthreads();  // protect s_cnt rewrite next iteration
    }

    const unsigned lamkey = prefix;  // exact key of sorted_desc[k]

    float sum = 0.f;
#pragma unroll
    for (int i = 0; i < PER; i++)
        if (key[i] >= lamkey) sum += val[i];
#pragma unroll
    for (int o = 16; o; o >>= 1)
        sum += __shfl_xor_sync(0xFFFFFFFFu, sum, o);
    if ((tid & 31) == 0) s_sum[tid >> 5] = sum;
    __syncthreads();

    if (tid == 0) {
        double tot = 0.0;
#pragma unroll
        for (int w = 0; w < 32; w++) tot += (double)s_sum[w];
        out[0] = (float)(tot / (double)N);
    }
}

// ---------------------------------------------------------------------------
extern "C" void kernel_launch(void* const* d_in, const int* in_sizes, int n_in,
                              void* d_out, int out_size)
{
    // Identify logits (larger element count) vs targets (smaller) robustly.
    int li = 0, ti = 1;
    if (n_in >= 2 && in_sizes[1] > in_sizes[0]) { li = 1; ti = 0; }

    const float* x   = (const float*)d_in[li];
    const void*  tgt = d_in[ti];
    float* out = (float*)d_out;

    const int N = in_sizes[ti];        // 32768
    const int C = in_sizes[li] / N;    // 1000
    const int k = (int)((double)N * 0.3);  // 9830

    detect_dtype_kernel<<<1, 1>>>((const int*)tgt, N);

    const int warps_per_block = 8;
    const int blocks = (N + warps_per_block - 1) / warps_per_block;
    ce_kernel<<<blocks, 256>>>(x, tgt, N, C);

    select_mean_kernel<<<1, 1024>>>(out, N, k);
}

// round 5
// speedup vs baseline: 2.1227x; 2.1227x over previous
#include <cuda_runtime.h>
#include <float.h>

// Scratch for per-sample CE losses (allocation-free: __device__ global).
__device__ float g_ce[32768];

// ---------------------------------------------------------------------------
// Kernel 1: per-row cross entropy + inline target-dtype detection.
// One warp per row, C<=1024 floats per row held in registers.
// Dtype probe: for little-endian int64 targets in [0,C), every odd 32-bit
// word is zero; for int32 targets P(first 32 odd words all zero) ~ 1e-96.
// Probe indices < 64 <= N are in-bounds for both layouts. Each warp probes
// the same 2 cache lines (L1-hot) -> globally consistent, ~free.
// ---------------------------------------------------------------------------
__global__ void __launch_bounds__(256)
ce_kernel(const float* __restrict__ x,
          const void* __restrict__ tgt,
          int N, int C)
{
    const int row  = blockIdx.x * 8 + (threadIdx.x >> 5);
    const int lane = threadIdx.x & 31;
    if (row >= N) return;

    const float4* rp = reinterpret_cast<const float4*>(x + (size_t)row * C);
    const int C4 = C >> 2;  // 250 for C=1000

    // Issue the big independent row loads first (MLP=8).
    float4 v[8];
#pragma unroll
    for (int i = 0; i < 8; i++) {
        int c = lane + (i << 5);
        if (c < C4) v[i] = rp[c];
        else        v[i] = make_float4(-FLT_MAX, -FLT_MAX, -FLT_MAX, -FLT_MAX);
    }

    // Dtype probe + target gather (overlaps with row loads in flight).
    const int* tw = reinterpret_cast<const int*>(tgt);
    int hiw = tw[2 * lane + 1];
    bool is64 = __all_sync(0xFFFFFFFFu, hiw == 0);

    float xt = 0.f;
    if (lane == 0) {
        long long t = is64 ? reinterpret_cast<const long long*>(tgt)[row]
                           : (long long)reinterpret_cast<const int*>(tgt)[row];
        if (t < 0)  t = 0;
        if (t >= C) t = C - 1;
        xt = x[(size_t)row * C + (int)t];
    }

    // warp max
    float m = -FLT_MAX;
#pragma unroll
    for (int i = 0; i < 8; i++)
        m = fmaxf(m, fmaxf(fmaxf(v[i].x, v[i].y), fmaxf(v[i].z, v[i].w)));
#pragma unroll
    for (int o = 16; o; o >>= 1)
        m = fmaxf(m, __shfl_xor_sync(0xFFFFFFFFu, m, o));

    // sum of exp(x - m); 4 accumulators break the serial FADD chain
    float s0 = 0.f, s1 = 0.f, s2 = 0.f, s3 = 0.f;
#pragma unroll
    for (int i = 0; i < 8; i++) {
        s0 += __expf(v[i].x - m);
        s1 += __expf(v[i].y - m);
        s2 += __expf(v[i].z - m);
        s3 += __expf(v[i].w - m);
    }
    float s = (s0 + s1) + (s2 + s3);
#pragma unroll
    for (int o = 16; o; o >>= 1)
        s += __shfl_xor_sync(0xFFFFFFFFu, s, o);

    if (lane == 0)
        g_ce[row] = m + __logf(s) - xt;
}

// ---------------------------------------------------------------------------
// Kernel 2: single CTA, 1024 threads x 32 values.
// Keys are bit-TRANSPOSED in registers once (32x32, Hacker's Delight), so
// each radix pass is popc(word & active) -- 2 ops/thread/pass, no spills
// (only m[32] stays live; ~40 regs/thread at 1024 threads).
// HD transpose orientation: result m[idx] holds key-bit (31-idx) across
// slots, with slot s at bit position (31-s).
// ---------------------------------------------------------------------------
__global__ void __launch_bounds__(1024)
select_mean_kernel(float* __restrict__ out, int N, int k)
{
    const int tid  = threadIdx.x;
    const int lane = tid & 31;
    const int wid  = tid >> 5;

    // Load keys (order-preserving uint transform of float bits).
    unsigned m[32];
#pragma unroll
    for (int i = 0; i < 32; i++) {
        int idx = tid + (i << 10);
        unsigned b = (idx < N) ? __float_as_uint(g_ce[idx]) : 0xFF800000u; // -inf pad
        m[i] = (b & 0x80000000u) ? ~b : (b | 0x80000000u);
    }

    // In-place 32x32 bit transpose.
#pragma unroll
    for (int st = 0; st < 5; st++) {
        const int j = 16 >> st;
        const unsigned msk = (st == 0) ? 0x0000FFFFu :
                             (st == 1) ? 0x00FF00FFu :
                             (st == 2) ? 0x0F0F0F0Fu :
                             (st == 3) ? 0x33333333u : 0x55555555u;
#pragma unroll
        for (int kk = 0; kk < 32; kk++) {
            if ((kk & j) == 0) {
                unsigned t2 = (m[kk] ^ (m[kk + j] >> j)) & msk;
                m[kk]     ^= t2;
                m[kk + j] ^= (t2 << j);
            }
        }
    }

    __shared__ int   s_warp[32];
    __shared__ int   s_flag;
    __shared__ float s_fsum[32];

    unsigned amask  = 0xFFFFFFFFu;  // slot s active <-> bit (31-s)
    unsigned lamkey = 0u;
    int rank = k;                   // maintained by thread 0 only

    // MSB-first exact radix select: m[idx] is key-bit (31-idx).
#pragma unroll
    for (int idx = 0; idx < 32; idx++) {
        int c = __popc(m[idx] & amask);
        c = __reduce_add_sync(0xFFFFFFFFu, c);
        if (lane == 0) s_warp[wid] = c;
        __syncthreads();
        if (wid == 0) {
            int tot = __reduce_add_sync(0xFFFFFFFFu, s_warp[lane]);
            if (lane == 0) {
                if (rank < tot) s_flag = 1;          // k-th largest in '1' group
                else { rank -= tot; s_flag = 0; }    // skip the '1' group
            }
        }
        __syncthreads();
        if (s_flag) { amask &=  m[idx]; lamkey |= (1u << (31 - idx)); }
        else        { amask &= ~m[idx]; }
    }

    // ge mask: slots with key >= lamkey (exact tie semantics of sorted_desc[k]).
    unsigned eq = 0xFFFFFFFFu, gt = 0u;
#pragma unroll
    for (int idx = 0; idx < 32; idx++) {
        if ((lamkey >> (31 - idx)) & 1u) {
            eq &= m[idx];
        } else {
            gt |= eq & m[idx];
            eq &= ~m[idx];
        }
    }
    const unsigned ge = gt | eq;

    // Masked sum: reload kept values (L2-resident) and reduce.
    float sum = 0.f;
#pragma unroll
    for (int i = 0; i < 32; i++) {
        int idx = tid + (i << 10);
        if (((ge >> (31 - i)) & 1u) && idx < N)
            sum += g_ce[idx];
    }
#pragma unroll
    for (int o = 16; o; o >>= 1)
        sum += __shfl_xor_sync(0xFFFFFFFFu, sum, o);
    if (lane == 0) s_fsum[wid] = sum;
    __syncthreads();

    if (tid == 0) {
        double tot = 0.0;
#pragma unroll
        for (int w = 0; w < 32; w++) tot += (double)s_fsum[w];
        out[0] = (float)(tot / (double)N);
    }
}

// ---------------------------------------------------------------------------
extern "C" void kernel_launch(void* const* d_in, const int* in_sizes, int n_in,
                              void* d_out, int out_size)
{
    // Identify logits (larger element count) vs targets (smaller).
    int li = 0, ti = 1;
    if (n_in >= 2 && in_sizes[1] > in_sizes[0]) { li = 1; ti = 0; }

    const float* x   = (const float*)d_in[li];
    const void*  tgt = d_in[ti];
    float* out = (float*)d_out;

    const int N = in_sizes[ti];            // 32768
    const int C = in_sizes[li] / N;        // 1000
    const int k = (int)((double)N * 0.3);  // 9830

    const int warps_per_block = 8;
    const int blocks = (N + warps_per_block - 1) / warps_per_block;
    ce_kernel<<<blocks, 256>>>(x, tgt, N, C);

    select_mean_kernel<<<1, 1024>>>(out, N, k);
}